// round 1
// baseline (speedup 1.0000x reference)
#include <cuda_runtime.h>
#include <cuda_bf16.h>
#include <math.h>

// ---------------------------------------------------------------------------
// CrossScaleAttention  (B=2, hidden=256, heads=8, head_dim=32)
//   high_feat: [2,128,64,64]   low_feat: [2,256,32,32]
// Output: concat(high_out [2,128,64,64], low_out [2,256,32,32]) as float
//
// Optimization used: conv1x1 and bilinear resize commute (both linear, resize
// weights sum to 1 so bias passes through), so all K/V convs run at 32x32.
// ---------------------------------------------------------------------------

#define B 2
#define HID 256
#define NHEAD 8
#define HD 32
#define SCALE 0.17677669529663687f  // 32^-0.5

// scratch layout (floats)
#define OFF_QH   0UL                     // [2,256,4096]
#define OFF_KL   2097152UL               // [2,256,4096]
#define OFF_VL   4194304UL               // [2,256,4096]
#define OFF_AH   6291456UL               // [2,256,4096]
#define OFF_KLS  8388608UL               // [2,256,1024]
#define OFF_VLS  8912896UL
#define OFF_QL   9437184UL
#define OFF_KH   9961472UL
#define OFF_VH   10485760UL
#define OFF_HD   11010048UL              // [2,128,1024]
#define OFF_AL   11272192UL              // [2,256,1024]
#define SCRATCH_FLOATS 11796480UL

__device__ float g_scratch[SCRATCH_FLOATS];

// ---------------------------------------------------------------------------
// Bilinear resize, matches jax.image.resize(method='bilinear', antialias=False)
// src/dst: [BC, Hs, Ws] -> [BC, Hd, Wd]
// ---------------------------------------------------------------------------
__global__ void resize_bilinear_k(const float* __restrict__ src, float* __restrict__ dst,
                                  int BC, int Hs, int Ws, int Hd, int Wd) {
    int idx = blockIdx.x * blockDim.x + threadIdx.x;
    int total = BC * Hd * Wd;
    if (idx >= total) return;
    int x = idx % Wd;
    int y = (idx / Wd) % Hd;
    int c = idx / (Wd * Hd);

    float sy = (y + 0.5f) * (float)Hs / (float)Hd - 0.5f;
    float sx = (x + 0.5f) * (float)Ws / (float)Wd - 0.5f;
    float fy = floorf(sy), fx = floorf(sx);
    float wy = sy - fy, wx = sx - fx;
    int y0 = (int)fy, x0 = (int)fx;
    int y0c = min(max(y0, 0), Hs - 1);
    int y1c = min(max(y0 + 1, 0), Hs - 1);
    int x0c = min(max(x0, 0), Ws - 1);
    int x1c = min(max(x0 + 1, 0), Ws - 1);

    const float* s = src + (size_t)c * Hs * Ws;
    float v00 = s[y0c * Ws + x0c];
    float v01 = s[y0c * Ws + x1c];
    float v10 = s[y1c * Ws + x0c];
    float v11 = s[y1c * Ws + x1c];
    float top = v00 + wx * (v01 - v00);
    float bot = v10 + wx * (v11 - v10);
    dst[idx] = top + wy * (bot - top);
}

// ---------------------------------------------------------------------------
// conv1x1 as GEMM: y[b,o,p] = sum_c w[o,c] * x[b,c,p] + bias[o]
// BM=BN=64, BK=16, 256 threads, 4x4 register tile. Dimensions assumed to
// divide tile sizes exactly (true for all call sites here).
// ---------------------------------------------------------------------------
__global__ void conv1x1_k(const float* __restrict__ x, const float* __restrict__ w,
                          const float* __restrict__ bias, float* __restrict__ y,
                          int C, int O, int P) {
    const int BM = 64, BN = 64, BK = 16;
    int b = blockIdx.z;
    x += (size_t)b * C * P;
    y += (size_t)b * O * P;
    int m0 = blockIdx.y * BM;
    int n0 = blockIdx.x * BN;

    __shared__ __align__(16) float Ws[BK][BM];
    __shared__ __align__(16) float Xs[BK][BN];

    int tid = threadIdx.x;
    int tx = tid & 15;       // n sub-tile
    int ty = tid >> 4;       // m sub-tile
    float acc[4][4] = {};

    for (int c0 = 0; c0 < C; c0 += BK) {
        // W tile: Ws[k][m] = w[(m0+m)*C + c0+k]
        #pragma unroll
        for (int i = 0; i < 4; i++) {
            int idx = tid + i * 256;          // 0..1023
            int m = idx >> 4, k = idx & 15;
            Ws[k][m] = w[(size_t)(m0 + m) * C + c0 + k];
        }
        // X tile: Xs[k][n] = x[(c0+k)*P + n0+n]
        #pragma unroll
        for (int i = 0; i < 4; i++) {
            int idx = tid + i * 256;
            int k = idx >> 6, n = idx & 63;
            Xs[k][n] = x[(size_t)(c0 + k) * P + n0 + n];
        }
        __syncthreads();
        #pragma unroll
        for (int k = 0; k < BK; k++) {
            float4 rm = *reinterpret_cast<const float4*>(&Ws[k][ty * 4]);
            float4 rn = *reinterpret_cast<const float4*>(&Xs[k][tx * 4]);
            float am[4] = {rm.x, rm.y, rm.z, rm.w};
            float an[4] = {rn.x, rn.y, rn.z, rn.w};
            #pragma unroll
            for (int i = 0; i < 4; i++)
                #pragma unroll
                for (int j = 0; j < 4; j++)
                    acc[i][j] += am[i] * an[j];
        }
        __syncthreads();
    }
    #pragma unroll
    for (int i = 0; i < 4; i++) {
        float bb = bias[m0 + ty * 4 + i];
        size_t row = (size_t)(m0 + ty * 4 + i) * P + n0 + tx * 4;
        #pragma unroll
        for (int j = 0; j < 4; j++)
            y[row + j] = acc[i][j] + bb;
    }
}

// ---------------------------------------------------------------------------
// Multi-head attention, q/k/v laid out [B, 256, N] (channel-major, spatial
// contiguous). One thread per query row, online softmax, KV tiles of 128 in
// shared memory, float4 broadcast reads.
// grid: (N/128, B*NHEAD), block: 128
// ---------------------------------------------------------------------------
__global__ __launch_bounds__(128) void attn_k(const float* __restrict__ q,
                                              const float* __restrict__ kk,
                                              const float* __restrict__ vv,
                                              float* __restrict__ out, int N) {
    int bh = blockIdx.y;
    int b = bh >> 3, h = bh & 7;
    size_t base = ((size_t)b * HID + h * HD) * N;
    int qi = blockIdx.x * 128 + threadIdx.x;

    __shared__ __align__(16) float Ks[128][36];   // stride 36: 16B-aligned rows, ok banks
    __shared__ __align__(16) float Vs[128][36];

    float qreg[HD];
    #pragma unroll
    for (int c = 0; c < HD; c++)
        qreg[c] = q[base + (size_t)c * N + qi] * SCALE;

    float m = -1e30f, l = 0.f;
    float acc[HD] = {};

    for (int kv0 = 0; kv0 < N; kv0 += 128) {
        // load KV tile: thread t loads key/value column kv0+t, all 32 channels
        #pragma unroll
        for (int c = 0; c < HD; c++) {
            Ks[threadIdx.x][c] = kk[base + (size_t)c * N + kv0 + threadIdx.x];
            Vs[threadIdx.x][c] = vv[base + (size_t)c * N + kv0 + threadIdx.x];
        }
        __syncthreads();

        for (int j = 0; j < 128; j++) {
            const float4* K4 = reinterpret_cast<const float4*>(&Ks[j][0]);
            float s0 = 0.f, s1 = 0.f, s2 = 0.f, s3 = 0.f;
            #pragma unroll
            for (int cc = 0; cc < 8; cc++) {
                float4 kv4 = K4[cc];
                s0 += qreg[cc * 4 + 0] * kv4.x;
                s1 += qreg[cc * 4 + 1] * kv4.y;
                s2 += qreg[cc * 4 + 2] * kv4.z;
                s3 += qreg[cc * 4 + 3] * kv4.w;
            }
            float s = (s0 + s1) + (s2 + s3);
            if (s > m) {
                float corr = __expf(m - s);
                #pragma unroll
                for (int c = 0; c < HD; c++) acc[c] *= corr;
                l *= corr;
                m = s;
            }
            float p = __expf(s - m);
            l += p;
            const float4* V4 = reinterpret_cast<const float4*>(&Vs[j][0]);
            #pragma unroll
            for (int cc = 0; cc < 8; cc++) {
                float4 v4 = V4[cc];
                acc[cc * 4 + 0] += p * v4.x;
                acc[cc * 4 + 1] += p * v4.y;
                acc[cc * 4 + 2] += p * v4.z;
                acc[cc * 4 + 3] += p * v4.w;
            }
        }
        __syncthreads();
    }

    float inv = 1.0f / l;
    #pragma unroll
    for (int c = 0; c < HD; c++)
        out[base + (size_t)c * N + qi] = acc[c] * inv;
}

// ---------------------------------------------------------------------------
extern "C" void kernel_launch(void* const* d_in, const int* in_sizes, int n_in,
                              void* d_out, int out_size) {
    const float* high = (const float*)d_in[0];   // [2,128,64,64]
    const float* low  = (const float*)d_in[1];   // [2,256,32,32]
    const float* qhw = (const float*)d_in[2];  const float* qhb = (const float*)d_in[3];
    const float* khw = (const float*)d_in[4];  const float* khb = (const float*)d_in[5];
    const float* vhw = (const float*)d_in[6];  const float* vhb = (const float*)d_in[7];
    const float* qlw = (const float*)d_in[8];  const float* qlb = (const float*)d_in[9];
    const float* klw = (const float*)d_in[10]; const float* klb = (const float*)d_in[11];
    const float* vlw = (const float*)d_in[12]; const float* vlb = (const float*)d_in[13];
    const float* ohw = (const float*)d_in[14]; const float* ohb = (const float*)d_in[15];
    const float* olw = (const float*)d_in[16]; const float* olb = (const float*)d_in[17];
    float* out = (float*)d_out;

    float* scr = nullptr;
    cudaGetSymbolAddress((void**)&scr, g_scratch);
    float* qh  = scr + OFF_QH;
    float* kl  = scr + OFF_KL;
    float* vl  = scr + OFF_VL;
    float* ah  = scr + OFF_AH;
    float* kls = scr + OFF_KLS;
    float* vls = scr + OFF_VLS;
    float* ql  = scr + OFF_QL;
    float* kh  = scr + OFF_KH;
    float* vh  = scr + OFF_VH;
    float* hd  = scr + OFF_HD;
    float* al  = scr + OFF_AL;

    // ---------------- high path ----------------
    // k_l/v_l at 32x32 (conv commutes with resize), then upsample to 64x64
    conv1x1_k<<<dim3(16, 4, B), 256>>>(low, klw, klb, kls, 256, 256, 1024);
    conv1x1_k<<<dim3(16, 4, B), 256>>>(low, vlw, vlb, vls, 256, 256, 1024);
    resize_bilinear_k<<<(B * 256 * 64 * 64 + 255) / 256, 256>>>(kls, kl, B * 256, 32, 32, 64, 64);
    resize_bilinear_k<<<(B * 256 * 64 * 64 + 255) / 256, 256>>>(vls, vl, B * 256, 32, 32, 64, 64);
    // q_h at 64x64
    conv1x1_k<<<dim3(64, 4, B), 256>>>(high, qhw, qhb, qh, 128, 256, 4096);
    // attention N=4096
    attn_k<<<dim3(32, B * NHEAD), 128>>>(qh, kl, vl, ah, 4096);
    // output projection -> d_out[0 : 2*128*4096]
    conv1x1_k<<<dim3(64, 2, B), 256>>>(ah, ohw, ohb, out, 256, 128, 4096);

    // ---------------- low path ----------------
    // downsample high_feat first (conv commutes with resize)
    resize_bilinear_k<<<(B * 128 * 32 * 32 + 255) / 256, 256>>>(high, hd, B * 128, 64, 64, 32, 32);
    conv1x1_k<<<dim3(16, 4, B), 256>>>(hd, khw, khb, kh, 128, 256, 1024);
    conv1x1_k<<<dim3(16, 4, B), 256>>>(hd, vhw, vhb, vh, 128, 256, 1024);
    conv1x1_k<<<dim3(16, 4, B), 256>>>(low, qlw, qlb, ql, 256, 256, 1024);
    // attention N=1024
    attn_k<<<dim3(8, B * NHEAD), 128>>>(ql, kh, vh, al, 1024);
    // output projection -> d_out[2*128*4096 : ]
    conv1x1_k<<<dim3(16, 4, B), 256>>>(al, olw, olb, out + (size_t)B * 128 * 4096, 256, 256, 1024);
}